// round 1
// baseline (speedup 1.0000x reference)
#include <cuda_runtime.h>
#include <math.h>

#define B_   2
#define S_   512
#define T_   1024        // B*S tokens
#define D_   1280
#define H_   20
#define DK_  64
#define L_   16
#define DI_  2560        // D_INNER
#define W1O_ 5120
#define VOC_ 1024
#define NP_  10
#define OUT_PER_B (VOC_*S_*NP_)   // 5242880

// ---------------- scratch (device globals; no allocation) ----------------
// layout in floats:
//  x:      0          (1,310,720)
//  h:      1,310,720
//  q:      2,621,440
//  k:      3,932,160
//  v:      5,242,880
//  o:      6,553,600
//  u:      7,864,320  (5,242,880)
//  gate:  13,107,200  (2,621,440)
//  scores:15,728,640  (10,485,760)
#define OFF_X  0
#define OFF_H  1310720
#define OFF_Q  2621440
#define OFF_K  3932160
#define OFF_V  5242880
#define OFF_O  6553600
#define OFF_U  7864320
#define OFF_G  13107200
#define OFF_S  15728640
__device__ float g_scratch[26214400];

// ---------------- embedding: x[t,d] = emb_b[d] + sum_c lat[b,c,n]*emb_w[d,c] -
__global__ void embed_kernel(const float* __restrict__ latents,
                             const float* __restrict__ emb_w,
                             const float* __restrict__ emb_b,
                             float* __restrict__ x) {
    int t = blockIdx.y;
    int d = blockIdx.x * 256 + threadIdx.x;
    __shared__ float lat[112];
    int b = t >> 9, n = t & 511;
    if (threadIdx.x < 112)
        lat[threadIdx.x] = latents[(size_t)b * 57344 + threadIdx.x * 512 + n];
    __syncthreads();
    float s = emb_b[d];
    const float* wrow = emb_w + (size_t)d * 112;
#pragma unroll 8
    for (int c = 0; c < 112; c++) s += lat[c] * wrow[c];
    x[(size_t)t * D_ + d] = s;
}

// ---------------- rmsnorm: one block per token ----------------
__global__ __launch_bounds__(256) void rmsnorm_kernel(const float* __restrict__ x,
                                                      const float* __restrict__ w,
                                                      float* __restrict__ out) {
    int t = blockIdx.x;
    const float* xr = x + (size_t)t * D_;
    float ss = 0.f;
    for (int i = threadIdx.x; i < D_; i += 256) { float v = xr[i]; ss += v * v; }
    __shared__ float red[8];
    float v = ss;
#pragma unroll
    for (int off = 16; off; off >>= 1) v += __shfl_down_sync(0xffffffffu, v, off);
    if ((threadIdx.x & 31) == 0) red[threadIdx.x >> 5] = v;
    __syncthreads();
    if (threadIdx.x == 0) {
        float r = 0.f;
#pragma unroll
        for (int i = 0; i < 8; i++) r += red[i];
        red[0] = r;
    }
    __syncthreads();
    float inv = 1.0f / sqrtf(red[0] / (float)D_ + 1e-5f);
    float* orow = out + (size_t)t * D_;
    for (int i = threadIdx.x; i < D_; i += 256) orow[i] = w[i] * (xr[i] * inv);
}

// ---------------- generic SGEMM NN: C[M,N] (+)= A[M,K] @ B[K,N] ----------------
// tiles: 64(M) x 128(N) x 16(K); 256 threads; 4x8 microtile
template <bool ACC>
__global__ __launch_bounds__(256) void sgemm_nn(const float* __restrict__ A,
                                                const float* __restrict__ Bm,
                                                float* __restrict__ C,
                                                int N, int K) {
    __shared__ float As[16][64];
    __shared__ float Bs[16][128];
    const int tid = threadIdx.x;
    const int m0 = blockIdx.y * 64;
    const int n0 = blockIdx.x * 128;
    const int a_row = tid >> 2, a_c4 = (tid & 3) << 2;
    const int b_row = tid >> 5, b_c4 = (tid & 31) << 2;
    const int tx = tid & 15, ty = tid >> 4;
    const float* Aptr = A + (size_t)(m0 + a_row) * K + a_c4;
    const float* Bptr = Bm + (size_t)b_row * N + n0 + b_c4;

    float acc[4][8];
#pragma unroll
    for (int i = 0; i < 4; i++)
#pragma unroll
        for (int j = 0; j < 8; j++) acc[i][j] = 0.f;

    for (int k0 = 0; k0 < K; k0 += 16) {
        float4 av  = *(const float4*)(Aptr + k0);
        float4 bv0 = *(const float4*)(Bptr + (size_t)k0 * N);
        float4 bv1 = *(const float4*)(Bptr + (size_t)(k0 + 8) * N);
        __syncthreads();
        As[a_c4 + 0][a_row] = av.x;
        As[a_c4 + 1][a_row] = av.y;
        As[a_c4 + 2][a_row] = av.z;
        As[a_c4 + 3][a_row] = av.w;
        *(float4*)&Bs[b_row][b_c4]     = bv0;
        *(float4*)&Bs[b_row + 8][b_c4] = bv1;
        __syncthreads();
#pragma unroll
        for (int kk = 0; kk < 16; kk++) {
            float4 a  = *(const float4*)&As[kk][ty * 4];
            float4 b0 = *(const float4*)&Bs[kk][tx * 8];
            float4 b1 = *(const float4*)&Bs[kk][tx * 8 + 4];
            float af[4] = {a.x, a.y, a.z, a.w};
            float bf[8] = {b0.x, b0.y, b0.z, b0.w, b1.x, b1.y, b1.z, b1.w};
#pragma unroll
            for (int i = 0; i < 4; i++)
#pragma unroll
                for (int j = 0; j < 8; j++) acc[i][j] += af[i] * bf[j];
        }
    }
#pragma unroll
    for (int i = 0; i < 4; i++) {
        float* cp = C + (size_t)(m0 + ty * 4 + i) * N + n0 + tx * 8;
        if (ACC) {
            float4 c0 = *(float4*)cp, c1 = *(float4*)(cp + 4);
            c0.x += acc[i][0]; c0.y += acc[i][1]; c0.z += acc[i][2]; c0.w += acc[i][3];
            c1.x += acc[i][4]; c1.y += acc[i][5]; c1.z += acc[i][6]; c1.w += acc[i][7];
            *(float4*)cp = c0; *(float4*)(cp + 4) = c1;
        } else {
            float4 c0 = {acc[i][0], acc[i][1], acc[i][2], acc[i][3]};
            float4 c1 = {acc[i][4], acc[i][5], acc[i][6], acc[i][7]};
            *(float4*)cp = c0; *(float4*)(cp + 4) = c1;
        }
    }
}

// ---------------- attention scores: scores[bh,i,j] = q.k/8 (+bias layer0) ------
__global__ __launch_bounds__(256) void attn_scores_kernel(const float* __restrict__ q,
                                                          const float* __restrict__ k,
                                                          const float* __restrict__ rel_bias,
                                                          float* __restrict__ scores,
                                                          int add_bias) {
    __shared__ float Qs[64][68];  // [dim][row]
    __shared__ float Ks[64][68];
    int tid = threadIdx.x;
    int bh = blockIdx.z, b = bh / H_, h = bh - b * H_;
    int i0 = blockIdx.y * 64, j0 = blockIdx.x * 64;
    const float* qbase = q + (size_t)(b * S_) * D_ + h * DK_;
    const float* kbase = k + (size_t)(b * S_) * D_ + h * DK_;
#pragma unroll
    for (int l = 0; l < 4; l++) {
        int idx = tid + l * 256;
        int row = idx >> 4;
        int c4 = (idx & 15) << 2;
        float4 vq = *(const float4*)(qbase + (size_t)(i0 + row) * D_ + c4);
        Qs[c4][row] = vq.x; Qs[c4 + 1][row] = vq.y; Qs[c4 + 2][row] = vq.z; Qs[c4 + 3][row] = vq.w;
        float4 vk = *(const float4*)(kbase + (size_t)(j0 + row) * D_ + c4);
        Ks[c4][row] = vk.x; Ks[c4 + 1][row] = vk.y; Ks[c4 + 2][row] = vk.z; Ks[c4 + 3][row] = vk.w;
    }
    __syncthreads();
    int tx = tid & 15, ty = tid >> 4;
    float acc[4][4];
#pragma unroll
    for (int i = 0; i < 4; i++)
#pragma unroll
        for (int j = 0; j < 4; j++) acc[i][j] = 0.f;
#pragma unroll 8
    for (int kk = 0; kk < 64; kk++) {
        float4 a = *(const float4*)&Qs[kk][ty * 4];
        float4 bq = *(const float4*)&Ks[kk][tx * 4];
        float af[4] = {a.x, a.y, a.z, a.w};
        float bf[4] = {bq.x, bq.y, bq.z, bq.w};
#pragma unroll
        for (int i = 0; i < 4; i++)
#pragma unroll
            for (int j = 0; j < 4; j++) acc[i][j] += af[i] * bf[j];
    }
#pragma unroll
    for (int ii = 0; ii < 4; ii++) {
        int i = i0 + ty * 4 + ii;
#pragma unroll
        for (int jj = 0; jj < 4; jj++) {
            int j = j0 + tx * 4 + jj;
            float s = acc[ii][jj] * 0.125f;
            if (add_bias) {
                int n = i - j;
                int ret = (n < 0) ? 16 : 0;
                int an = (n < 0) ? -n : n;
                int val;
                if (an < 8) val = an;
                else {
                    val = 8 + (int)(logf((float)an / 8.0f) / logf(16.0f) * 8.0f);
                    if (val > 15) val = 15;
                }
                s += rel_bias[(ret + val) * H_ + h];
            }
            scores[(size_t)(bh * S_ + i) * S_ + j] = s;
        }
    }
}

// ---------------- softmax over last dim (512) ----------------
__global__ __launch_bounds__(256) void softmax_kernel(float* __restrict__ scores) {
    size_t row = blockIdx.x;
    float* p = scores + row * S_;
    int tid = threadIdx.x;
    float v0 = p[tid], v1 = p[tid + 256];
    float m = fmaxf(v0, v1);
    __shared__ float redm[8];
    __shared__ float reds[8];
#pragma unroll
    for (int off = 16; off; off >>= 1) m = fmaxf(m, __shfl_down_sync(0xffffffffu, m, off));
    if ((tid & 31) == 0) redm[tid >> 5] = m;
    __syncthreads();
    if (tid == 0) {
        float mm = redm[0];
#pragma unroll
        for (int i = 1; i < 8; i++) mm = fmaxf(mm, redm[i]);
        redm[0] = mm;
    }
    __syncthreads();
    float bm = redm[0];
    float e0 = expf(v0 - bm), e1 = expf(v1 - bm);
    float s = e0 + e1;
#pragma unroll
    for (int off = 16; off; off >>= 1) s += __shfl_down_sync(0xffffffffu, s, off);
    if ((tid & 31) == 0) reds[tid >> 5] = s;
    __syncthreads();
    if (tid == 0) {
        float t = 0.f;
#pragma unroll
        for (int i = 0; i < 8; i++) t += reds[i];
        reds[0] = t;
    }
    __syncthreads();
    float inv = 1.0f / reds[0];
    p[tid] = e0 * inv;
    p[tid + 256] = e1 * inv;
}

// ---------------- o = attn @ v  (per b,h: 512x64x512) ----------------
__global__ __launch_bounds__(256) void attn_av_kernel(const float* __restrict__ attn,
                                                      const float* __restrict__ v,
                                                      float* __restrict__ o) {
    __shared__ float As[32][68];  // [k][m]
    __shared__ float Vs[32][64];  // [k][n]
    int tid = threadIdx.x;
    int bh = blockIdx.y, b = bh / H_, h = bh - b * H_;
    int i0 = blockIdx.x * 64;
    const float* abase = attn + (size_t)bh * S_ * S_;
    const float* vbase = v + (size_t)(b * S_) * D_ + h * DK_;
    int tx = tid & 15, ty = tid >> 4;
    float acc[4][4];
#pragma unroll
    for (int i = 0; i < 4; i++)
#pragma unroll
        for (int j = 0; j < 4; j++) acc[i][j] = 0.f;

    for (int k0 = 0; k0 < S_; k0 += 32) {
        __syncthreads();
#pragma unroll
        for (int l = 0; l < 2; l++) {
            int idx = tid + l * 256;
            int row = idx >> 3;
            int c4 = (idx & 7) << 2;
            float4 a = *(const float4*)(abase + (size_t)(i0 + row) * S_ + k0 + c4);
            As[c4][row] = a.x; As[c4 + 1][row] = a.y; As[c4 + 2][row] = a.z; As[c4 + 3][row] = a.w;
            int vr = idx >> 4;
            int vc4 = (idx & 15) << 2;
            *(float4*)&Vs[vr][vc4] = *(const float4*)(vbase + (size_t)(k0 + vr) * D_ + vc4);
        }
        __syncthreads();
#pragma unroll 8
        for (int kk = 0; kk < 32; kk++) {
            float4 a = *(const float4*)&As[kk][ty * 4];
            float4 bv = *(const float4*)&Vs[kk][tx * 4];
            float af[4] = {a.x, a.y, a.z, a.w};
            float bf[4] = {bv.x, bv.y, bv.z, bv.w};
#pragma unroll
            for (int i = 0; i < 4; i++)
#pragma unroll
                for (int j = 0; j < 4; j++) acc[i][j] += af[i] * bf[j];
        }
    }
#pragma unroll
    for (int ii = 0; ii < 4; ii++) {
        float4 c = {acc[ii][0], acc[ii][1], acc[ii][2], acc[ii][3]};
        *(float4*)(o + (size_t)(b * S_ + i0 + ty * 4 + ii) * D_ + h * DK_ + tx * 4) = c;
    }
}

// ---------------- GEGLU: gate[t,j] = u[t,j] * gelu(u[t,2560+j]) ----------------
__global__ void geglu_kernel(const float* __restrict__ u, float* __restrict__ g) {
    int idx = blockIdx.x * 256 + threadIdx.x;   // over T_*DI_
    int t = idx / DI_, j = idx - t * DI_;
    float a = u[(size_t)t * W1O_ + j];
    float gg = u[(size_t)t * W1O_ + DI_ + j];
    float g3 = gg * gg * gg;
    float th = tanhf(0.7978845608028654f * (gg + 0.044715f * g3));
    g[idx] = a * (0.5f * gg * (1.0f + th));
}

// ---------------- classifier: out scatter of X @ W^T + b ----------------
// A: [1024,1280] (normed x), W: [10240,1280], bias [10240]
// out[b, v, s*10+p] = sum_d A[(b,s),d]*W[v*10+p,d] + bias[v*10+p]
__global__ __launch_bounds__(256) void classifier_kernel(const float* __restrict__ A,
                                                         const float* __restrict__ W,
                                                         const float* __restrict__ bias,
                                                         float* __restrict__ out) {
    __shared__ float As[16][64];
    __shared__ float Bs[16][132];
    const int tid = threadIdx.x;
    const int m0 = blockIdx.y * 64;
    const int n0 = blockIdx.x * 128;
    const int a_row = tid >> 2, a_c4 = (tid & 3) << 2;
    const int tx = tid & 15, ty = tid >> 4;
    const int K = D_;
    float acc[4][8];
#pragma unroll
    for (int i = 0; i < 4; i++)
#pragma unroll
        for (int j = 0; j < 8; j++) acc[i][j] = 0.f;

    for (int k0 = 0; k0 < K; k0 += 16) {
        float4 av = *(const float4*)(A + (size_t)(m0 + a_row) * K + k0 + a_c4);
        float4 bv[2];
#pragma unroll
        for (int l = 0; l < 2; l++) {
            int idx = tid + l * 256;
            int row = idx >> 2;
            int c4 = (idx & 3) << 2;
            bv[l] = *(const float4*)(W + (size_t)(n0 + row) * K + k0 + c4);
        }
        __syncthreads();
        As[a_c4 + 0][a_row] = av.x;
        As[a_c4 + 1][a_row] = av.y;
        As[a_c4 + 2][a_row] = av.z;
        As[a_c4 + 3][a_row] = av.w;
#pragma unroll
        for (int l = 0; l < 2; l++) {
            int idx = tid + l * 256;
            int row = idx >> 2;
            int c4 = (idx & 3) << 2;
            Bs[c4 + 0][row] = bv[l].x;
            Bs[c4 + 1][row] = bv[l].y;
            Bs[c4 + 2][row] = bv[l].z;
            Bs[c4 + 3][row] = bv[l].w;
        }
        __syncthreads();
#pragma unroll
        for (int kk = 0; kk < 16; kk++) {
            float4 a  = *(const float4*)&As[kk][ty * 4];
            float4 b0 = *(const float4*)&Bs[kk][tx * 8];
            float4 b1 = *(const float4*)&Bs[kk][tx * 8 + 4];
            float af[4] = {a.x, a.y, a.z, a.w};
            float bf[8] = {b0.x, b0.y, b0.z, b0.w, b1.x, b1.y, b1.z, b1.w};
#pragma unroll
            for (int i = 0; i < 4; i++)
#pragma unroll
                for (int j = 0; j < 8; j++) acc[i][j] += af[i] * bf[j];
        }
    }
#pragma unroll
    for (int ii = 0; ii < 4; ii++) {
        int t = m0 + ty * 4 + ii;
        int bb = t >> 9, s = t & 511;
#pragma unroll
        for (int jj = 0; jj < 8; jj++) {
            int oidx = n0 + tx * 8 + jj;
            int vv = oidx / NP_;
            int pp = oidx - vv * NP_;
            out[(size_t)bb * OUT_PER_B + (size_t)vv * (S_ * NP_) + s * NP_ + pp] =
                acc[ii][jj] + bias[oidx];
        }
    }
}

// ---------------- host launch ----------------
extern "C" void kernel_launch(void* const* d_in, const int* in_sizes, int n_in,
                              void* d_out, int out_size) {
    const float* latents    = (const float*)d_in[0];
    const float* emb_w      = (const float*)d_in[1];
    const float* emb_b      = (const float*)d_in[2];
    const float* norm_w     = (const float*)d_in[3];
    const float* wq         = (const float*)d_in[4];
    const float* wk         = (const float*)d_in[5];
    const float* wv         = (const float*)d_in[6];
    const float* wo         = (const float*)d_in[7];
    const float* w1         = (const float*)d_in[8];
    const float* w2         = (const float*)d_in[9];
    const float* rel_bias   = (const float*)d_in[10];
    const float* norm_out_w = (const float*)d_in[11];
    const float* cls_w      = (const float*)d_in[12];
    const float* cls_b      = (const float*)d_in[13];
    float* out = (float*)d_out;

    float* ws = nullptr;
    cudaGetSymbolAddress((void**)&ws, g_scratch);
    float* x      = ws + OFF_X;
    float* h      = ws + OFF_H;
    float* q      = ws + OFF_Q;
    float* k      = ws + OFF_K;
    float* v      = ws + OFF_V;
    float* o      = ws + OFF_O;
    float* u      = ws + OFF_U;
    float* gate   = ws + OFF_G;
    float* scores = ws + OFF_S;

    // embedding
    embed_kernel<<<dim3(D_ / 256, T_), 256>>>(latents, emb_w, emb_b, x);

    const dim3 gD(D_ / 128, T_ / 64);      // N=1280 gemms
    const dim3 gW1(W1O_ / 128, T_ / 64);   // N=5120
    const dim3 gSc(S_ / 64, S_ / 64, B_ * H_);
    const dim3 gAv(S_ / 64, B_ * H_);

    for (int l = 0; l < L_; l++) {
        const float* nw  = norm_w + (size_t)l * D_;
        const float* wql = wq + (size_t)l * D_ * D_;
        const float* wkl = wk + (size_t)l * D_ * D_;
        const float* wvl = wv + (size_t)l * D_ * D_;
        const float* wol = wo + (size_t)l * D_ * D_;
        const float* w1l = w1 + (size_t)l * D_ * W1O_;
        const float* w2l = w2 + (size_t)l * DI_ * D_;

        rmsnorm_kernel<<<T_, 256>>>(x, nw, h);
        sgemm_nn<false><<<gD, 256>>>(h, wql, q, D_, D_);
        sgemm_nn<false><<<gD, 256>>>(h, wkl, k, D_, D_);
        sgemm_nn<false><<<gD, 256>>>(h, wvl, v, D_, D_);
        attn_scores_kernel<<<gSc, 256>>>(q, k, rel_bias, scores, l == 0 ? 1 : 0);
        softmax_kernel<<<B_ * H_ * S_, 256>>>(scores);
        attn_av_kernel<<<gAv, 256>>>(scores, v, o);
        sgemm_nn<true><<<gD, 256>>>(o, wol, x, D_, D_);
        sgemm_nn<false><<<gW1, 256>>>(x, w1l, u, W1O_, D_);
        geglu_kernel<<<(T_ * DI_) / 256, 256>>>(u, gate);
        sgemm_nn<true><<<gD, 256>>>(gate, w2l, x, D_, DI_);
    }

    rmsnorm_kernel<<<T_, 256>>>(x, norm_out_w, h);
    classifier_kernel<<<dim3((VOC_ * NP_) / 128, T_ / 64), 256>>>(h, cls_w, cls_b, out);
}

// round 2
// speedup vs baseline: 1.0018x; 1.0018x over previous
#include <cuda_runtime.h>
#include <math.h>

#define B_   2
#define S_   512
#define T_   1024        // B*S tokens
#define D_   1280
#define H_   20
#define DK_  64
#define L_   16
#define DI_  2560        // D_INNER
#define W1O_ 5120
#define VOC_ 1024
#define NP_  10
#define OUT_PER_B (VOC_*S_*NP_)   // 5242880

// ---------------- scratch (device globals; no allocation) ----------------
// layout in floats:
//  x:      0          (1,310,720)
//  h:      1,310,720
//  q:      2,621,440
//  k:      3,932,160
//  v:      5,242,880
//  o:      6,553,600
//  u:      7,864,320  (5,242,880)
//  gate:  13,107,200  (2,621,440)
//  scores:15,728,640  (10,485,760)
#define OFF_X  0
#define OFF_H  1310720
#define OFF_Q  2621440
#define OFF_K  3932160
#define OFF_V  5242880
#define OFF_O  6553600
#define OFF_U  7864320
#define OFF_G  13107200
#define OFF_S  15728640
__device__ float g_scratch[26214400];

// ---------------- embedding: x[t,d] = emb_b[d] + sum_c lat[b,c,n]*emb_w[d,c] -
__global__ void embed_kernel(const float* __restrict__ latents,
                             const float* __restrict__ emb_w,
                             const float* __restrict__ emb_b,
                             float* __restrict__ x) {
    int t = blockIdx.y;
    int d = blockIdx.x * 256 + threadIdx.x;
    __shared__ float lat[112];
    int b = t >> 9, n = t & 511;
    if (threadIdx.x < 112)
        lat[threadIdx.x] = latents[(size_t)b * 57344 + threadIdx.x * 512 + n];
    __syncthreads();
    float s = emb_b[d];
    const float* wrow = emb_w + (size_t)d * 112;
#pragma unroll 8
    for (int c = 0; c < 112; c++) s += lat[c] * wrow[c];
    x[(size_t)t * D_ + d] = s;
}

// ---------------- rmsnorm: one block per token ----------------
__global__ __launch_bounds__(256) void rmsnorm_kernel(const float* __restrict__ x,
                                                      const float* __restrict__ w,
                                                      float* __restrict__ out) {
    int t = blockIdx.x;
    const float* xr = x + (size_t)t * D_;
    float ss = 0.f;
    for (int i = threadIdx.x; i < D_; i += 256) { float v = xr[i]; ss += v * v; }
    __shared__ float red[8];
    float v = ss;
#pragma unroll
    for (int off = 16; off; off >>= 1) v += __shfl_down_sync(0xffffffffu, v, off);
    if ((threadIdx.x & 31) == 0) red[threadIdx.x >> 5] = v;
    __syncthreads();
    if (threadIdx.x == 0) {
        float r = 0.f;
#pragma unroll
        for (int i = 0; i < 8; i++) r += red[i];
        red[0] = r;
    }
    __syncthreads();
    float inv = 1.0f / sqrtf(red[0] / (float)D_ + 1e-5f);
    float* orow = out + (size_t)t * D_;
    for (int i = threadIdx.x; i < D_; i += 256) orow[i] = w[i] * (xr[i] * inv);
}

// ---------------- generic SGEMM NN: C[M,N] (+)= A[M,K] @ B[K,N] ----------------
// tiles: 64(M) x 128(N) x 16(K); 256 threads; 4x8 microtile
template <bool ACC>
__global__ __launch_bounds__(256) void sgemm_nn(const float* __restrict__ A,
                                                const float* __restrict__ Bm,
                                                float* __restrict__ C,
                                                int N, int K) {
    __shared__ float As[16][64];
    __shared__ float Bs[16][128];
    const int tid = threadIdx.x;
    const int m0 = blockIdx.y * 64;
    const int n0 = blockIdx.x * 128;
    const int a_row = tid >> 2, a_c4 = (tid & 3) << 2;
    const int b_row = tid >> 5, b_c4 = (tid & 31) << 2;
    const int tx = tid & 15, ty = tid >> 4;
    const float* Aptr = A + (size_t)(m0 + a_row) * K + a_c4;
    const float* Bptr = Bm + (size_t)b_row * N + n0 + b_c4;

    float acc[4][8];
#pragma unroll
    for (int i = 0; i < 4; i++)
#pragma unroll
        for (int j = 0; j < 8; j++) acc[i][j] = 0.f;

    for (int k0 = 0; k0 < K; k0 += 16) {
        float4 av  = *(const float4*)(Aptr + k0);
        float4 bv0 = *(const float4*)(Bptr + (size_t)k0 * N);
        float4 bv1 = *(const float4*)(Bptr + (size_t)(k0 + 8) * N);
        __syncthreads();
        As[a_c4 + 0][a_row] = av.x;
        As[a_c4 + 1][a_row] = av.y;
        As[a_c4 + 2][a_row] = av.z;
        As[a_c4 + 3][a_row] = av.w;
        *(float4*)&Bs[b_row][b_c4]     = bv0;
        *(float4*)&Bs[b_row + 8][b_c4] = bv1;
        __syncthreads();
#pragma unroll
        for (int kk = 0; kk < 16; kk++) {
            float4 a  = *(const float4*)&As[kk][ty * 4];
            float4 b0 = *(const float4*)&Bs[kk][tx * 8];
            float4 b1 = *(const float4*)&Bs[kk][tx * 8 + 4];
            float af[4] = {a.x, a.y, a.z, a.w};
            float bf[8] = {b0.x, b0.y, b0.z, b0.w, b1.x, b1.y, b1.z, b1.w};
#pragma unroll
            for (int i = 0; i < 4; i++)
#pragma unroll
                for (int j = 0; j < 8; j++) acc[i][j] += af[i] * bf[j];
        }
    }
#pragma unroll
    for (int i = 0; i < 4; i++) {
        float* cp = C + (size_t)(m0 + ty * 4 + i) * N + n0 + tx * 8;
        if (ACC) {
            float4 c0 = *(float4*)cp, c1 = *(float4*)(cp + 4);
            c0.x += acc[i][0]; c0.y += acc[i][1]; c0.z += acc[i][2]; c0.w += acc[i][3];
            c1.x += acc[i][4]; c1.y += acc[i][5]; c1.z += acc[i][6]; c1.w += acc[i][7];
            *(float4*)cp = c0; *(float4*)(cp + 4) = c1;
        } else {
            float4 c0 = {acc[i][0], acc[i][1], acc[i][2], acc[i][3]};
            float4 c1 = {acc[i][4], acc[i][5], acc[i][6], acc[i][7]};
            *(float4*)cp = c0; *(float4*)(cp + 4) = c1;
        }
    }
}

// ---------------- attention scores: scores[bh,i,j] = q.k/8 (+bias layer0) ------
__global__ __launch_bounds__(256) void attn_scores_kernel(const float* __restrict__ q,
                                                          const float* __restrict__ k,
                                                          const float* __restrict__ rel_bias,
                                                          float* __restrict__ scores,
                                                          int add_bias) {
    __shared__ float Qs[64][68];  // [dim][row]
    __shared__ float Ks[64][68];
    int tid = threadIdx.x;
    int bh = blockIdx.z, b = bh / H_, h = bh - b * H_;
    int i0 = blockIdx.y * 64, j0 = blockIdx.x * 64;
    const float* qbase = q + (size_t)(b * S_) * D_ + h * DK_;
    const float* kbase = k + (size_t)(b * S_) * D_ + h * DK_;
#pragma unroll
    for (int l = 0; l < 4; l++) {
        int idx = tid + l * 256;
        int row = idx >> 4;
        int c4 = (idx & 15) << 2;
        float4 vq = *(const float4*)(qbase + (size_t)(i0 + row) * D_ + c4);
        Qs[c4][row] = vq.x; Qs[c4 + 1][row] = vq.y; Qs[c4 + 2][row] = vq.z; Qs[c4 + 3][row] = vq.w;
        float4 vk = *(const float4*)(kbase + (size_t)(j0 + row) * D_ + c4);
        Ks[c4][row] = vk.x; Ks[c4 + 1][row] = vk.y; Ks[c4 + 2][row] = vk.z; Ks[c4 + 3][row] = vk.w;
    }
    __syncthreads();
    int tx = tid & 15, ty = tid >> 4;
    float acc[4][4];
#pragma unroll
    for (int i = 0; i < 4; i++)
#pragma unroll
        for (int j = 0; j < 4; j++) acc[i][j] = 0.f;
#pragma unroll 8
    for (int kk = 0; kk < 64; kk++) {
        float4 a = *(const float4*)&Qs[kk][ty * 4];
        float4 bq = *(const float4*)&Ks[kk][tx * 4];
        float af[4] = {a.x, a.y, a.z, a.w};
        float bf[4] = {bq.x, bq.y, bq.z, bq.w};
#pragma unroll
        for (int i = 0; i < 4; i++)
#pragma unroll
            for (int j = 0; j < 4; j++) acc[i][j] += af[i] * bf[j];
    }
#pragma unroll
    for (int ii = 0; ii < 4; ii++) {
        int i = i0 + ty * 4 + ii;
#pragma unroll
        for (int jj = 0; jj < 4; jj++) {
            int j = j0 + tx * 4 + jj;
            float s = acc[ii][jj] * 0.125f;
            if (add_bias) {
                int n = i - j;
                int ret = (n < 0) ? 16 : 0;
                int an = (n < 0) ? -n : n;
                int val;
                if (an < 8) val = an;
                else {
                    val = 8 + (int)(logf((float)an / 8.0f) / logf(16.0f) * 8.0f);
                    if (val > 15) val = 15;
                }
                s += rel_bias[(ret + val) * H_ + h];
            }
            scores[(size_t)(bh * S_ + i) * S_ + j] = s;
        }
    }
}

// ---------------- softmax over last dim (512) ----------------
__global__ __launch_bounds__(256) void softmax_kernel(float* __restrict__ scores) {
    size_t row = blockIdx.x;
    float* p = scores + row * S_;
    int tid = threadIdx.x;
    float v0 = p[tid], v1 = p[tid + 256];
    float m = fmaxf(v0, v1);
    __shared__ float redm[8];
    __shared__ float reds[8];
#pragma unroll
    for (int off = 16; off; off >>= 1) m = fmaxf(m, __shfl_down_sync(0xffffffffu, m, off));
    if ((tid & 31) == 0) redm[tid >> 5] = m;
    __syncthreads();
    if (tid == 0) {
        float mm = redm[0];
#pragma unroll
        for (int i = 1; i < 8; i++) mm = fmaxf(mm, redm[i]);
        redm[0] = mm;
    }
    __syncthreads();
    float bm = redm[0];
    float e0 = expf(v0 - bm), e1 = expf(v1 - bm);
    float s = e0 + e1;
#pragma unroll
    for (int off = 16; off; off >>= 1) s += __shfl_down_sync(0xffffffffu, s, off);
    if ((tid & 31) == 0) reds[tid >> 5] = s;
    __syncthreads();
    if (tid == 0) {
        float t = 0.f;
#pragma unroll
        for (int i = 0; i < 8; i++) t += reds[i];
        reds[0] = t;
    }
    __syncthreads();
    float inv = 1.0f / reds[0];
    p[tid] = e0 * inv;
    p[tid + 256] = e1 * inv;
}

// ---------------- o = attn @ v  (per b,h: 512x64x512) ----------------
__global__ __launch_bounds__(256) void attn_av_kernel(const float* __restrict__ attn,
                                                      const float* __restrict__ v,
                                                      float* __restrict__ o) {
    __shared__ float As[32][68];  // [k][m]
    __shared__ float Vs[32][64];  // [k][n]
    int tid = threadIdx.x;
    int bh = blockIdx.y, b = bh / H_, h = bh - b * H_;
    int i0 = blockIdx.x * 64;
    const float* abase = attn + (size_t)bh * S_ * S_;
    const float* vbase = v + (size_t)(b * S_) * D_ + h * DK_;
    int tx = tid & 15, ty = tid >> 4;
    float acc[4][4];
#pragma unroll
    for (int i = 0; i < 4; i++)
#pragma unroll
        for (int j = 0; j < 4; j++) acc[i][j] = 0.f;

    for (int k0 = 0; k0 < S_; k0 += 32) {
        __syncthreads();
#pragma unroll
        for (int l = 0; l < 2; l++) {
            int idx = tid + l * 256;
            int row = idx >> 3;
            int c4 = (idx & 7) << 2;
            float4 a = *(const float4*)(abase + (size_t)(i0 + row) * S_ + k0 + c4);
            As[c4][row] = a.x; As[c4 + 1][row] = a.y; As[c4 + 2][row] = a.z; As[c4 + 3][row] = a.w;
            int vr = idx >> 4;
            int vc4 = (idx & 15) << 2;
            *(float4*)&Vs[vr][vc4] = *(const float4*)(vbase + (size_t)(k0 + vr) * D_ + vc4);
        }
        __syncthreads();
#pragma unroll 8
        for (int kk = 0; kk < 32; kk++) {
            float4 a = *(const float4*)&As[kk][ty * 4];
            float4 bv = *(const float4*)&Vs[kk][tx * 4];
            float af[4] = {a.x, a.y, a.z, a.w};
            float bf[4] = {bv.x, bv.y, bv.z, bv.w};
#pragma unroll
            for (int i = 0; i < 4; i++)
#pragma unroll
                for (int j = 0; j < 4; j++) acc[i][j] += af[i] * bf[j];
        }
    }
#pragma unroll
    for (int ii = 0; ii < 4; ii++) {
        float4 c = {acc[ii][0], acc[ii][1], acc[ii][2], acc[ii][3]};
        *(float4*)(o + (size_t)(b * S_ + i0 + ty * 4 + ii) * D_ + h * DK_ + tx * 4) = c;
    }
}

// ---------------- GEGLU: gate[t,j] = u[t,j] * gelu(u[t,2560+j]) ----------------
__global__ void geglu_kernel(const float* __restrict__ u, float* __restrict__ g) {
    int idx = blockIdx.x * 256 + threadIdx.x;   // over T_*DI_
    int t = idx / DI_, j = idx - t * DI_;
    float a = u[(size_t)t * W1O_ + j];
    float gg = u[(size_t)t * W1O_ + DI_ + j];
    float g3 = gg * gg * gg;
    float th = tanhf(0.7978845608028654f * (gg + 0.044715f * g3));
    g[idx] = a * (0.5f * gg * (1.0f + th));
}

// ---------------- classifier: out scatter of X @ W^T + b ----------------
// A: [1024,1280] (normed x), W: [10240,1280], bias [10240]
// out[b, v, s*10+p] = sum_d A[(b,s),d]*W[v*10+p,d] + bias[v*10+p]
__global__ __launch_bounds__(256) void classifier_kernel(const float* __restrict__ A,
                                                         const float* __restrict__ W,
                                                         const float* __restrict__ bias,
                                                         float* __restrict__ out) {
    __shared__ float As[16][64];
    __shared__ float Bs[16][132];
    const int tid = threadIdx.x;
    const int m0 = blockIdx.y * 64;
    const int n0 = blockIdx.x * 128;
    const int a_row = tid >> 2, a_c4 = (tid & 3) << 2;
    const int tx = tid & 15, ty = tid >> 4;
    const int K = D_;
    float acc[4][8];
#pragma unroll
    for (int i = 0; i < 4; i++)
#pragma unroll
        for (int j = 0; j < 8; j++) acc[i][j] = 0.f;

    for (int k0 = 0; k0 < K; k0 += 16) {
        float4 av = *(const float4*)(A + (size_t)(m0 + a_row) * K + k0 + a_c4);
        float4 bv[2];
#pragma unroll
        for (int l = 0; l < 2; l++) {
            int idx = tid + l * 256;
            int row = idx >> 2;
            int c4 = (idx & 3) << 2;
            bv[l] = *(const float4*)(W + (size_t)(n0 + row) * K + k0 + c4);
        }
        __syncthreads();
        As[a_c4 + 0][a_row] = av.x;
        As[a_c4 + 1][a_row] = av.y;
        As[a_c4 + 2][a_row] = av.z;
        As[a_c4 + 3][a_row] = av.w;
#pragma unroll
        for (int l = 0; l < 2; l++) {
            int idx = tid + l * 256;
            int row = idx >> 2;
            int c4 = (idx & 3) << 2;
            Bs[c4 + 0][row] = bv[l].x;
            Bs[c4 + 1][row] = bv[l].y;
            Bs[c4 + 2][row] = bv[l].z;
            Bs[c4 + 3][row] = bv[l].w;
        }
        __syncthreads();
#pragma unroll
        for (int kk = 0; kk < 16; kk++) {
            float4 a  = *(const float4*)&As[kk][ty * 4];
            float4 b0 = *(const float4*)&Bs[kk][tx * 8];
            float4 b1 = *(const float4*)&Bs[kk][tx * 8 + 4];
            float af[4] = {a.x, a.y, a.z, a.w};
            float bf[8] = {b0.x, b0.y, b0.z, b0.w, b1.x, b1.y, b1.z, b1.w};
#pragma unroll
            for (int i = 0; i < 4; i++)
#pragma unroll
                for (int j = 0; j < 8; j++) acc[i][j] += af[i] * bf[j];
        }
    }
#pragma unroll
    for (int ii = 0; ii < 4; ii++) {
        int t = m0 + ty * 4 + ii;
        int bb = t >> 9, s = t & 511;
#pragma unroll
        for (int jj = 0; jj < 8; jj++) {
            int oidx = n0 + tx * 8 + jj;
            int vv = oidx / NP_;
            int pp = oidx - vv * NP_;
            out[(size_t)bb * OUT_PER_B + (size_t)vv * (S_ * NP_) + s * NP_ + pp] =
                acc[ii][jj] + bias[oidx];
        }
    }
}

// ---------------- host launch ----------------
extern "C" void kernel_launch(void* const* d_in, const int* in_sizes, int n_in,
                              void* d_out, int out_size) {
    const float* latents    = (const float*)d_in[0];
    const float* emb_w      = (const float*)d_in[1];
    const float* emb_b      = (const float*)d_in[2];
    const float* norm_w     = (const float*)d_in[3];
    const float* wq         = (const float*)d_in[4];
    const float* wk         = (const float*)d_in[5];
    const float* wv         = (const float*)d_in[6];
    const float* wo         = (const float*)d_in[7];
    const float* w1         = (const float*)d_in[8];
    const float* w2         = (const float*)d_in[9];
    const float* rel_bias   = (const float*)d_in[10];
    const float* norm_out_w = (const float*)d_in[11];
    const float* cls_w      = (const float*)d_in[12];
    const float* cls_b      = (const float*)d_in[13];
    float* out = (float*)d_out;

    float* ws = nullptr;
    cudaGetSymbolAddress((void**)&ws, g_scratch);
    float* x      = ws + OFF_X;
    float* h      = ws + OFF_H;
    float* q      = ws + OFF_Q;
    float* k      = ws + OFF_K;
    float* v      = ws + OFF_V;
    float* o      = ws + OFF_O;
    float* u      = ws + OFF_U;
    float* gate   = ws + OFF_G;
    float* scores = ws + OFF_S;

    // embedding
    embed_kernel<<<dim3(D_ / 256, T_), 256>>>(latents, emb_w, emb_b, x);

    const dim3 gD(D_ / 128, T_ / 64);      // N=1280 gemms
    const dim3 gW1(W1O_ / 128, T_ / 64);   // N=5120
    const dim3 gSc(S_ / 64, S_ / 64, B_ * H_);
    const dim3 gAv(S_ / 64, B_ * H_);

    for (int l = 0; l < L_; l++) {
        const float* nw  = norm_w + (size_t)l * D_;
        const float* wql = wq + (size_t)l * D_ * D_;
        const float* wkl = wk + (size_t)l * D_ * D_;
        const float* wvl = wv + (size_t)l * D_ * D_;
        const float* wol = wo + (size_t)l * D_ * D_;
        const float* w1l = w1 + (size_t)l * D_ * W1O_;
        const float* w2l = w2 + (size_t)l * DI_ * D_;

        rmsnorm_kernel<<<T_, 256>>>(x, nw, h);
        sgemm_nn<false><<<gD, 256>>>(h, wql, q, D_, D_);
        sgemm_nn<false><<<gD, 256>>>(h, wkl, k, D_, D_);
        sgemm_nn<false><<<gD, 256>>>(h, wvl, v, D_, D_);
        attn_scores_kernel<<<gSc, 256>>>(q, k, rel_bias, scores, l == 0 ? 1 : 0);
        softmax_kernel<<<B_ * H_ * S_, 256>>>(scores);
        attn_av_kernel<<<gAv, 256>>>(scores, v, o);
        sgemm_nn<true><<<gD, 256>>>(o, wol, x, D_, D_);
        sgemm_nn<false><<<gW1, 256>>>(x, w1l, u, W1O_, D_);
        geglu_kernel<<<(T_ * DI_) / 256, 256>>>(u, gate);
        sgemm_nn<true><<<gD, 256>>>(gate, w2l, x, D_, DI_);
    }

    rmsnorm_kernel<<<T_, 256>>>(x, norm_out_w, h);
    classifier_kernel<<<dim3((VOC_ * NP_) / 128, T_ / 64), 256>>>(h, cls_w, cls_b, out);
}